// round 9
// baseline (speedup 1.0000x reference)
#include <cuda_runtime.h>
#include <cuda_bf16.h>

#define BZc 8
#define Nc 4096
#define CFc 64
#define NSc 1024
#define Kc 64
#define EPSc 1e-5f
#define NEGc -1e8f
#define Rc 0.2f
#define CANDMAX 1280

typedef unsigned long long u64t;

// ---------------- f32x2 packed helpers (sm_100+) ----------------
__device__ __forceinline__ u64t f2pk(float lo, float hi) {
    u64t r; asm("mov.b64 %0,{%1,%2};" : "=l"(r) : "f"(lo), "f"(hi)); return r;
}
__device__ __forceinline__ u64t f2dup(float a) {
    u64t r; asm("mov.b64 %0,{%1,%1};" : "=l"(r) : "f"(a)); return r;
}
__device__ __forceinline__ void f2unpk(u64t v, float& lo, float& hi) {
    asm("mov.b64 {%0,%1},%2;" : "=f"(lo), "=f"(hi) : "l"(v));
}
__device__ __forceinline__ u64t f2add(u64t a, u64t b) {
    u64t r; asm("add.rn.f32x2 %0,%1,%2;" : "=l"(r) : "l"(a), "l"(b)); return r;
}
__device__ __forceinline__ u64t f2mul(u64t a, u64t b) {
    u64t r; asm("mul.rn.f32x2 %0,%1,%2;" : "=l"(r) : "l"(a), "l"(b)); return r;
}
__device__ __forceinline__ void f2fma(u64t& acc, u64t w, u64t a) {
    asm("fma.rn.f32x2 %0,%1,%2,%0;" : "+l"(acc) : "l"(w), "l"(a));
}

// ---------------- scratch (no allocs allowed) ----------------
__device__ int   g_fps[BZc * NSc];
__device__ int   g_nbr[BZc * NSc * Kc];          // idx | (in_radius ? 0 : 0x80000000)
__device__ __align__(16) float g_w0[67 * 64];
__device__ __align__(16) float g_bb0[64];
__device__ __align__(16) float g_w1[64 * 64];
__device__ __align__(16) float g_bb1[64];
__device__ __align__(16) float g_w2[64 * 128];
__device__ __align__(16) float g_bb2[128];

// ---------------- fold BN (eval) into weights ----------------
__global__ void fold_kernel(
    const float* __restrict__ W0, const float* __restrict__ b0, const float* __restrict__ g0,
    const float* __restrict__ be0, const float* __restrict__ rm0, const float* __restrict__ rv0,
    const float* __restrict__ W1, const float* __restrict__ b1, const float* __restrict__ g1,
    const float* __restrict__ be1, const float* __restrict__ rm1, const float* __restrict__ rv1,
    const float* __restrict__ W2, const float* __restrict__ b2, const float* __restrict__ g2,
    const float* __restrict__ be2, const float* __restrict__ rm2, const float* __restrict__ rv2)
{
    int t = blockIdx.x * blockDim.x + threadIdx.x;
    int stride = gridDim.x * blockDim.x;
    for (int i = t; i < 67 * 64; i += stride) {
        int o = i & 63;
        g_w0[i] = W0[i] * (g0[o] * rsqrtf(rv0[o] + EPSc));
    }
    for (int i = t; i < 64; i += stride) {
        float sc = g0[i] * rsqrtf(rv0[i] + EPSc);
        g_bb0[i] = (b0[i] - rm0[i]) * sc + be0[i];
    }
    for (int i = t; i < 64 * 64; i += stride) {
        int o = i & 63;
        g_w1[i] = W1[i] * (g1[o] * rsqrtf(rv1[o] + EPSc));
    }
    for (int i = t; i < 64; i += stride) {
        float sc = g1[i] * rsqrtf(rv1[i] + EPSc);
        g_bb1[i] = (b1[i] - rm1[i]) * sc + be1[i];
    }
    for (int i = t; i < 64 * 128; i += stride) {
        int o = i & 127;
        g_w2[i] = W2[i] * (g2[o] * rsqrtf(rv2[o] + EPSc));
    }
    for (int i = t; i < 128; i += stride) {
        float sc = g2[i] * rsqrtf(rv2[i] + EPSc);
        g_bb2[i] = (b2[i] - rm2[i]) * sc + be2[i];
    }
}

// ---------------- farthest point sampling ----------------
__global__ void __launch_bounds__(256) fps_kernel(const float* __restrict__ pos,
                                                  float* __restrict__ out_sp)
{
    extern __shared__ float sm[];
    float* px = sm;
    float* py = sm + Nc;
    float* pz = sm + 2 * Nc;
    __shared__ unsigned rv_[2][8];
    __shared__ int      ri_[2][8];

    int b = blockIdx.x;
    int tid = threadIdx.x;
    int lane = tid & 31, wid = tid >> 5;
    const float* pb = pos + (size_t)b * Nc * 3;

    u64t xp[8], yp[8], zp[8];
    float ld[16];
#pragma unroll
    for (int p = 0; p < 8; p++) {
        int j0 = tid + 256 * (2 * p);
        int j1 = tid + 256 * (2 * p + 1);
        float x0 = pb[3 * j0], y0 = pb[3 * j0 + 1], z0 = pb[3 * j0 + 2];
        float x1 = pb[3 * j1], y1 = pb[3 * j1 + 1], z1 = pb[3 * j1 + 2];
        px[j0] = x0; py[j0] = y0; pz[j0] = z0;
        px[j1] = x1; py[j1] = y1; pz[j1] = z1;
        xp[p] = f2pk(x0, x1); yp[p] = f2pk(y0, y1); zp[p] = f2pk(z0, z1);
        ld[2 * p] = 1e10f; ld[2 * p + 1] = 1e10f;
    }
    __syncthreads();

    int cur = 0;
    for (int s = 0; s < NSc; s++) {
        float cx = px[cur], cy = py[cur], cz = pz[cur];
        if (tid == 0) {
            g_fps[b * NSc + s] = cur;
            out_sp[(b * NSc + s) * 3 + 0] = cx;
            out_sp[(b * NSc + s) * 3 + 1] = cy;
            out_sp[(b * NSc + s) * 3 + 2] = cz;
        }
        u64t ncx = f2dup(-cx), ncy = f2dup(-cy), ncz = f2dup(-cz);
#pragma unroll
        for (int p = 0; p < 8; p++) {
            u64t dx = f2add(xp[p], ncx);
            u64t dy = f2add(yp[p], ncy);
            u64t dz = f2add(zp[p], ncz);
            u64t d2 = f2add(f2add(f2mul(dx, dx), f2mul(dy, dy)), f2mul(dz, dz));
            float s0, s1;
            f2unpk(d2, s0, s1);
            ld[2 * p] = fminf(ld[2 * p], s0);
            ld[2 * p + 1] = fminf(ld[2 * p + 1], s1);
        }
        // tournament-tree argmax over 16 values, lowest index wins ties
        float v8[8]; int i8[8];
#pragma unroll
        for (int i = 0; i < 8; i++) {
            float a = ld[2 * i], bb2_ = ld[2 * i + 1];
            bool t = bb2_ > a;
            v8[i] = t ? bb2_ : a;
            i8[i] = tid + 256 * (2 * i + (t ? 1 : 0));
        }
        float v4[4]; int i4[4];
#pragma unroll
        for (int i = 0; i < 4; i++) {
            bool t = v8[2 * i + 1] > v8[2 * i];
            v4[i] = t ? v8[2 * i + 1] : v8[2 * i];
            i4[i] = t ? i8[2 * i + 1] : i8[2 * i];
        }
        float va, vb; int ia, ib;
        { bool t = v4[1] > v4[0]; va = t ? v4[1] : v4[0]; ia = t ? i4[1] : i4[0]; }
        { bool t = v4[3] > v4[2]; vb = t ? v4[3] : v4[2]; ib = t ? i4[3] : i4[2]; }
        bool tf = vb > va;
        float bv = tf ? vb : va;
        int   bi = tf ? ib : ia;

        unsigned bvb = __float_as_uint(bv);
        unsigned m = __reduce_max_sync(0xffffffffu, bvb);
        unsigned cand = (bvb == m) ? (unsigned)bi : 0x7FFFFFFFu;
        unsigned wmin = __reduce_min_sync(0xffffffffu, cand);

        int par = s & 1;
        if (lane == 0) { rv_[par][wid] = m; ri_[par][wid] = (int)wmin; }
        __syncthreads();
        unsigned v2 = (lane < 8) ? rv_[par][lane] : 0u;
        unsigned j2 = (lane < 8) ? (unsigned)ri_[par][lane] : 0x7FFFFFFFu;
        unsigned m2 = __reduce_max_sync(0xffffffffu, v2);
        unsigned c2 = (v2 == m2) ? j2 : 0x7FFFFFFFu;
        cur = (int)__reduce_min_sync(0xffffffffu, c2);
    }
}

// ---------------- exact top-K via bit-space bisection + pairwise rank ----------------
__global__ void __launch_bounds__(256) select_kernel(const float* __restrict__ pos)
{
    __shared__ int wred[2][8];
    __shared__ int s_cnt;
    __shared__ unsigned cand_v[CANDMAX];
    __shared__ int      cand_i[CANDMAX];

    int b = blockIdx.y, s = blockIdx.x, tid = threadIdx.x;
    int lane = tid & 31, wid = tid >> 5;
    const float* pb = pos + (size_t)b * Nc * 3;
    int ci = g_fps[b * NSc + s];
    float sx = pb[3 * ci], sy = pb[3 * ci + 1], sz = pb[3 * ci + 2];
    float ss = __fadd_rn(__fadd_rn(__fmul_rn(sx, sx), __fmul_rn(sy, sy)), __fmul_rn(sz, sz));

    if (tid == 0) s_cnt = 0;

    unsigned vr[16];
#pragma unroll
    for (int i = 0; i < 16; i++) {
        int j = tid + 256 * i;
        float x = pb[3 * j], y = pb[3 * j + 1], z = pb[3 * j + 2];
        float pp = __fadd_rn(__fadd_rn(__fmul_rn(x, x), __fmul_rn(y, y)), __fmul_rn(z, z));
        float dot = __fadd_rn(__fadd_rn(__fmul_rn(sx, x), __fmul_rn(sy, y)), __fmul_rn(sz, z));
        float d2 = __fadd_rn(__fadd_rn(ss, pp), __fmul_rn(-2.0f, dot));
        float dd = sqrtf(fmaxf(d2, 0.0f));
        vr[i] = __float_as_uint(dd);
    }

    // bisection, one barrier per iter (parity-buffered warp sums, redundant block sum)
    unsigned lo = 0u, hi = 0x40000000u;
    unsigned thr = hi;
    for (int it = 0; it < 32; it++) {
        unsigned m = (lo + hi) >> 1;
        int c = 0;
#pragma unroll
        for (int i = 0; i < 16; i++) c += (vr[i] < m) ? 1 : 0;
        c = (int)__reduce_add_sync(0xffffffffu, (unsigned)c);
        int par = it & 1;
        if (lane == 0) wred[par][wid] = c;
        __syncthreads();
        int tot = (int)__reduce_add_sync(0xffffffffu, (lane < 8) ? (unsigned)wred[par][lane] : 0u);
        if (tot >= Kc && tot <= 256) { thr = m; break; }
        if (tot < Kc) lo = m; else hi = m;
        if (hi - lo <= 1) { thr = hi; break; }
    }

#pragma unroll
    for (int i = 0; i < 16; i++) {
        if (vr[i] < thr) {
            int p = atomicAdd(&s_cnt, 1);
            if (p < CANDMAX) { cand_v[p] = vr[i]; cand_i[p] = tid + 256 * i; }
        }
    }
    __syncthreads();
    int c = s_cnt; if (c > CANDMAX) c = CANDMAX;

    int off = (b * NSc + s) * Kc;
    for (int q0 = tid; q0 < c; q0 += 256) {
        unsigned vi = cand_v[q0];
        int ji = cand_i[q0];
        int r = 0;
        for (int q = 0; q < c; q++) {
            unsigned vq = cand_v[q];
            int jq = cand_i[q];
            r += (vq < vi || (vq == vi && jq < ji)) ? 1 : 0;
        }
        if (r < Kc) {
            float ddv = __uint_as_float(vi);
            g_nbr[off + r] = ji | (ddv <= Rc ? 0 : 0x80000000);
        }
    }
}

// ---------------- fused MLP (67->64->64->128) + masked max pool ----------------
// Transposed activations [ch][k]; layer 3 split into two k-passes of 8 u64
// accumulators to fit 64 regs -> 4 CTAs/SM.
__global__ void __launch_bounds__(256, 4) mlp_kernel(const float* __restrict__ x,
                                                     const float* __restrict__ pos,
                                                     float* __restrict__ out,
                                                     const float* __restrict__ sp)
{
    __shared__ float As[67 * 68];   // [ch][k], stride 68
    __shared__ float Bs[64 * 68];   // [ch][k]
    __shared__ float Mx[8 * 128];
    __shared__ int nidx[64];
    __shared__ unsigned char smask[64];
    __shared__ float scp[3];

    int b = blockIdx.y, s = blockIdx.x, tid = threadIdx.x;
    int w = tid >> 5, lane = tid & 31;

    if (tid < 64) {
        int e = g_nbr[(b * NSc + s) * Kc + tid];
        nidx[tid] = e & 0x7FFFFFFF;
        smask[tid] = (e >= 0) ? 1 : 0;
    }
    if (tid < 3) scp[tid] = sp[(b * NSc + s) * 3 + tid];
    __syncthreads();

    const float* xb = x + (size_t)b * Nc * CFc;
    const float* pb = pos + (size_t)b * Nc * 3;
    for (int i = tid; i < 64 * 67; i += 256) {
        int k = i / 67, ch = i - k * 67;
        int id = nidx[k];
        float v = (ch < 3) ? (pb[3 * id + ch] - scp[ch]) : xb[(size_t)id * CFc + (ch - 3)];
        As[ch * 68 + k] = v;
    }
    __syncthreads();

    // ---- layer 1: 67 -> 64. warp slice: 16 o x 32 k; thread: 4k x 4o ----
    {
        int o0 = (w & 3) * 16 + (lane & 3) * 4;
        int k0 = (w >> 2) * 32 + (lane >> 2) * 4;
        float4 b4 = *(const float4*)(g_bb0 + o0);
        u64t aL[4], aH[4];
#pragma unroll
        for (int i = 0; i < 4; i++) { aL[i] = f2pk(b4.x, b4.y); aH[i] = f2pk(b4.z, b4.w); }
        for (int ch = 0; ch < 67; ch++) {
            float4 a = *(const float4*)(As + ch * 68 + k0);
            ulonglong2 wv = *(const ulonglong2*)(g_w0 + ch * 64 + o0);
            u64t d0 = f2dup(a.x); f2fma(aL[0], wv.x, d0); f2fma(aH[0], wv.y, d0);
            u64t d1 = f2dup(a.y); f2fma(aL[1], wv.x, d1); f2fma(aH[1], wv.y, d1);
            u64t d2 = f2dup(a.z); f2fma(aL[2], wv.x, d2); f2fma(aH[2], wv.y, d2);
            u64t d3 = f2dup(a.w); f2fma(aL[3], wv.x, d3); f2fma(aH[3], wv.y, d3);
        }
        float r[4][4];
#pragma unroll
        for (int i = 0; i < 4; i++) {
            f2unpk(aL[i], r[i][0], r[i][1]);
            f2unpk(aH[i], r[i][2], r[i][3]);
#pragma unroll
            for (int j = 0; j < 4; j++) r[i][j] = fmaxf(r[i][j], 0.f);
        }
#pragma unroll
        for (int j = 0; j < 4; j++)
            *(float4*)(Bs + (o0 + j) * 68 + k0) = make_float4(r[0][j], r[1][j], r[2][j], r[3][j]);
    }
    __syncthreads();

    // ---- layer 2: 64 -> 64, same tiling, Bs -> As ----
    {
        int o0 = (w & 3) * 16 + (lane & 3) * 4;
        int k0 = (w >> 2) * 32 + (lane >> 2) * 4;
        float4 b4 = *(const float4*)(g_bb1 + o0);
        u64t aL[4], aH[4];
#pragma unroll
        for (int i = 0; i < 4; i++) { aL[i] = f2pk(b4.x, b4.y); aH[i] = f2pk(b4.z, b4.w); }
        for (int ch = 0; ch < 64; ch++) {
            float4 a = *(const float4*)(Bs + ch * 68 + k0);
            ulonglong2 wv = *(const ulonglong2*)(g_w1 + ch * 64 + o0);
            u64t d0 = f2dup(a.x); f2fma(aL[0], wv.x, d0); f2fma(aH[0], wv.y, d0);
            u64t d1 = f2dup(a.y); f2fma(aL[1], wv.x, d1); f2fma(aH[1], wv.y, d1);
            u64t d2 = f2dup(a.z); f2fma(aL[2], wv.x, d2); f2fma(aH[2], wv.y, d2);
            u64t d3 = f2dup(a.w); f2fma(aL[3], wv.x, d3); f2fma(aH[3], wv.y, d3);
        }
        float r[4][4];
#pragma unroll
        for (int i = 0; i < 4; i++) {
            f2unpk(aL[i], r[i][0], r[i][1]);
            f2unpk(aH[i], r[i][2], r[i][3]);
#pragma unroll
            for (int j = 0; j < 4; j++) r[i][j] = fmaxf(r[i][j], 0.f);
        }
#pragma unroll
        for (int j = 0; j < 4; j++)
            *(float4*)(As + (o0 + j) * 68 + k0) = make_float4(r[0][j], r[1][j], r[2][j], r[3][j]);
    }
    __syncthreads();

    // ---- layer 3: 64 -> 128. warp slice: 32 o x 32 k; TWO k-passes of 4k x 4o ----
    {
        int o0 = (w & 3) * 32 + (lane & 7) * 4;
        int kw = (w >> 2) * 32;
        float4 b4 = *(const float4*)(g_bb2 + o0);
        float4 mx = make_float4(NEGc, NEGc, NEGc, NEGc);
#pragma unroll
        for (int pass = 0; pass < 2; pass++) {
            int k0 = kw + pass * 16 + (lane >> 3) * 4;
            u64t aL[4], aH[4];
#pragma unroll
            for (int i = 0; i < 4; i++) { aL[i] = f2pk(b4.x, b4.y); aH[i] = f2pk(b4.z, b4.w); }
            for (int ch = 0; ch < 64; ch++) {
                float4 a = *(const float4*)(As + ch * 68 + k0);
                ulonglong2 wv = *(const ulonglong2*)(g_w2 + ch * 128 + o0);
                u64t d0 = f2dup(a.x); f2fma(aL[0], wv.x, d0); f2fma(aH[0], wv.y, d0);
                u64t d1 = f2dup(a.y); f2fma(aL[1], wv.x, d1); f2fma(aH[1], wv.y, d1);
                u64t d2 = f2dup(a.z); f2fma(aL[2], wv.x, d2); f2fma(aH[2], wv.y, d2);
                u64t d3 = f2dup(a.w); f2fma(aL[3], wv.x, d3); f2fma(aH[3], wv.y, d3);
            }
#pragma unroll
            for (int i = 0; i < 4; i++) {
                if (smask[k0 + i]) {
                    float r0, r1, r2, r3;
                    f2unpk(aL[i], r0, r1);
                    f2unpk(aH[i], r2, r3);
                    mx.x = fmaxf(mx.x, fmaxf(r0, 0.f));
                    mx.y = fmaxf(mx.y, fmaxf(r1, 0.f));
                    mx.z = fmaxf(mx.z, fmaxf(r2, 0.f));
                    mx.w = fmaxf(mx.w, fmaxf(r3, 0.f));
                }
            }
        }
        int row = (w >> 2) * 4 + (lane >> 3);
        *(float4*)(Mx + row * 128 + o0) = mx;
    }
    __syncthreads();

    if (tid < 128) {
        float v = NEGc;
#pragma unroll
        for (int q = 0; q < 8; q++) v = fmaxf(v, Mx[q * 128 + tid]);
        out[(size_t)(b * NSc + s) * 128 + tid] = v;
    }
}

// ---------------- launch ----------------
extern "C" void kernel_launch(void* const* d_in, const int* in_sizes, int n_in,
                              void* d_out, int out_size)
{
    const float* x   = (const float*)d_in[0];
    const float* pos = (const float*)d_in[1];
    const float* W0 = (const float*)d_in[2];
    const float* b0 = (const float*)d_in[3];
    const float* g0 = (const float*)d_in[4];
    const float* be0 = (const float*)d_in[5];
    const float* rm0 = (const float*)d_in[6];
    const float* rv0 = (const float*)d_in[7];
    const float* W1 = (const float*)d_in[8];
    const float* b1 = (const float*)d_in[9];
    const float* g1 = (const float*)d_in[10];
    const float* be1 = (const float*)d_in[11];
    const float* rm1 = (const float*)d_in[12];
    const float* rv1 = (const float*)d_in[13];
    const float* W2 = (const float*)d_in[14];
    const float* b2 = (const float*)d_in[15];
    const float* g2 = (const float*)d_in[16];
    const float* be2 = (const float*)d_in[17];
    const float* rm2 = (const float*)d_in[18];
    const float* rv2 = (const float*)d_in[19];

    float* out = (float*)d_out;
    float* out_sp = out + (size_t)BZc * NSc * 128;  // tuple output 2: sampled_pos

    const int FPS_SMEM = 3 * Nc * 4;  // 48 KB dynamic

    cudaFuncSetAttribute(fps_kernel, cudaFuncAttributeMaxDynamicSharedMemorySize, FPS_SMEM);

    fold_kernel<<<40, 256>>>(W0, b0, g0, be0, rm0, rv0,
                             W1, b1, g1, be1, rm1, rv1,
                             W2, b2, g2, be2, rm2, rv2);
    fps_kernel<<<BZc, 256, FPS_SMEM>>>(pos, out_sp);
    select_kernel<<<dim3(NSc, BZc), 256>>>(pos);
    mlp_kernel<<<dim3(NSc, BZc), 256>>>(x, pos, out, out_sp);
}

// round 11
// speedup vs baseline: 1.0417x; 1.0417x over previous
#include <cuda_runtime.h>
#include <cuda_bf16.h>

#define BZc 8
#define Nc 4096
#define CFc 64
#define NSc 1024
#define Kc 64
#define EPSc 1e-5f
#define NEGc -1e8f
#define Rc 0.2f
#define CANDMAX 1280

typedef unsigned long long u64t;

// ---------------- f32x2 packed helpers (sm_100+) ----------------
__device__ __forceinline__ u64t f2pk(float lo, float hi) {
    u64t r; asm("mov.b64 %0,{%1,%2};" : "=l"(r) : "f"(lo), "f"(hi)); return r;
}
__device__ __forceinline__ u64t f2dup(float a) {
    u64t r; asm("mov.b64 %0,{%1,%1};" : "=l"(r) : "f"(a)); return r;
}
__device__ __forceinline__ void f2unpk(u64t v, float& lo, float& hi) {
    asm("mov.b64 {%0,%1},%2;" : "=f"(lo), "=f"(hi) : "l"(v));
}
__device__ __forceinline__ u64t f2add(u64t a, u64t b) {
    u64t r; asm("add.rn.f32x2 %0,%1,%2;" : "=l"(r) : "l"(a), "l"(b)); return r;
}
__device__ __forceinline__ u64t f2mul(u64t a, u64t b) {
    u64t r; asm("mul.rn.f32x2 %0,%1,%2;" : "=l"(r) : "l"(a), "l"(b)); return r;
}
__device__ __forceinline__ void f2fma(u64t& acc, u64t w, u64t a) {
    asm("fma.rn.f32x2 %0,%1,%2,%0;" : "+l"(acc) : "l"(w), "l"(a));
}

// ---------------- scratch (no allocs allowed) ----------------
__device__ int g_fps[BZc * NSc];
__device__ int g_prog[BZc];                      // fps progress counter per batch
__device__ __align__(16) float g_w0[67 * 64];
__device__ __align__(16) float g_bb0[64];
__device__ __align__(16) float g_w1[64 * 64];
__device__ __align__(16) float g_bb1[64];
__device__ __align__(16) float g_w2[64 * 128];
__device__ __align__(16) float g_bb2[128];

// ---------------- fold BN (eval) into weights ----------------
__global__ void fold_kernel(
    const float* __restrict__ W0, const float* __restrict__ b0, const float* __restrict__ g0,
    const float* __restrict__ be0, const float* __restrict__ rm0, const float* __restrict__ rv0,
    const float* __restrict__ W1, const float* __restrict__ b1, const float* __restrict__ g1,
    const float* __restrict__ be1, const float* __restrict__ rm1, const float* __restrict__ rv1,
    const float* __restrict__ W2, const float* __restrict__ b2, const float* __restrict__ g2,
    const float* __restrict__ be2, const float* __restrict__ rm2, const float* __restrict__ rv2)
{
    int t = blockIdx.x * blockDim.x + threadIdx.x;
    int stride = gridDim.x * blockDim.x;
    for (int i = t; i < 67 * 64; i += stride) {
        int o = i & 63;
        g_w0[i] = W0[i] * (g0[o] * rsqrtf(rv0[o] + EPSc));
    }
    for (int i = t; i < 64; i += stride) {
        float sc = g0[i] * rsqrtf(rv0[i] + EPSc);
        g_bb0[i] = (b0[i] - rm0[i]) * sc + be0[i];
    }
    for (int i = t; i < 64 * 64; i += stride) {
        int o = i & 63;
        g_w1[i] = W1[i] * (g1[o] * rsqrtf(rv1[o] + EPSc));
    }
    for (int i = t; i < 64; i += stride) {
        float sc = g1[i] * rsqrtf(rv1[i] + EPSc);
        g_bb1[i] = (b1[i] - rm1[i]) * sc + be1[i];
    }
    for (int i = t; i < 64 * 128; i += stride) {
        int o = i & 127;
        g_w2[i] = W2[i] * (g2[o] * rsqrtf(rv2[o] + EPSc));
    }
    for (int i = t; i < 128; i += stride) {
        float sc = g2[i] * rsqrtf(rv2[i] + EPSc);
        g_bb2[i] = (b2[i] - rm2[i]) * sc + be2[i];
    }
}

// ---------------- shared-memory overlay ----------------
struct SFps { float px[Nc]; float py[Nc]; float pz[Nc]; };
struct SSel { unsigned cand_v[CANDMAX]; int cand_i[CANDMAX]; };
struct SMlp { float As[67 * 68]; float Bs[64 * 68]; float Mx[8 * 128]; };
union SU { SFps f; SSel sel; SMlp m; };

// ---------------- mega kernel: fps producers + (select+mlp) consumers ----------------
__global__ void __launch_bounds__(256, 3) mega_kernel(const float* __restrict__ x,
                                                      const float* __restrict__ pos,
                                                      float* __restrict__ out,
                                                      float* __restrict__ out_sp)
{
    extern __shared__ char raw[];
    SU* u = (SU*)raw;
    __shared__ unsigned rv_[2][8];
    __shared__ int      ri_[2][8];
    __shared__ int s_cnt, s_ci;
    __shared__ int nidx[64];
    __shared__ unsigned char smask[64];
    __shared__ float scp[3];

    int bid = blockIdx.x;
    int tid = threadIdx.x;
    int lane = tid & 31, wid = tid >> 5;

    if (bid < BZc) {
        // ================= FPS producer =================
        int b = bid;
        float* px = u->f.px;
        float* py = u->f.py;
        float* pz = u->f.pz;
        const float* pb = pos + (size_t)b * Nc * 3;

        u64t xp[8], yp[8], zp[8];
        float ld[16];
#pragma unroll
        for (int p = 0; p < 8; p++) {
            int j0 = tid + 256 * (2 * p);
            int j1 = tid + 256 * (2 * p + 1);
            float x0 = pb[3 * j0], y0 = pb[3 * j0 + 1], z0 = pb[3 * j0 + 2];
            float x1 = pb[3 * j1], y1 = pb[3 * j1 + 1], z1 = pb[3 * j1 + 2];
            px[j0] = x0; py[j0] = y0; pz[j0] = z0;
            px[j1] = x1; py[j1] = y1; pz[j1] = z1;
            xp[p] = f2pk(x0, x1); yp[p] = f2pk(y0, y1); zp[p] = f2pk(z0, z1);
            ld[2 * p] = 1e10f; ld[2 * p + 1] = 1e10f;
        }
        __syncthreads();

        int cur = 0;
        for (int s = 0; s < NSc; s++) {
            float cx = px[cur], cy = py[cur], cz = pz[cur];
            if (tid == 0) {
                g_fps[b * NSc + s] = cur;
                out_sp[(b * NSc + s) * 3 + 0] = cx;
                out_sp[(b * NSc + s) * 3 + 1] = cy;
                out_sp[(b * NSc + s) * 3 + 2] = cz;
                int np = s + 1;
                asm volatile("st.release.gpu.u32 [%0], %1;" :: "l"(g_prog + b), "r"(np) : "memory");
            }
            u64t ncx = f2dup(-cx), ncy = f2dup(-cy), ncz = f2dup(-cz);
#pragma unroll
            for (int p = 0; p < 8; p++) {
                u64t dx = f2add(xp[p], ncx);
                u64t dy = f2add(yp[p], ncy);
                u64t dz = f2add(zp[p], ncz);
                u64t d2 = f2add(f2add(f2mul(dx, dx), f2mul(dy, dy)), f2mul(dz, dz));
                float s0, s1;
                f2unpk(d2, s0, s1);
                ld[2 * p] = fminf(ld[2 * p], s0);
                ld[2 * p + 1] = fminf(ld[2 * p + 1], s1);
            }
            // tournament-tree argmax over 16 values, lowest index wins ties
            float v8[8]; int i8[8];
#pragma unroll
            for (int i = 0; i < 8; i++) {
                float a = ld[2 * i], bb2_ = ld[2 * i + 1];
                bool t = bb2_ > a;
                v8[i] = t ? bb2_ : a;
                i8[i] = tid + 256 * (2 * i + (t ? 1 : 0));
            }
            float v4[4]; int i4[4];
#pragma unroll
            for (int i = 0; i < 4; i++) {
                bool t = v8[2 * i + 1] > v8[2 * i];
                v4[i] = t ? v8[2 * i + 1] : v8[2 * i];
                i4[i] = t ? i8[2 * i + 1] : i8[2 * i];
            }
            float va, vb; int ia, ib;
            { bool t = v4[1] > v4[0]; va = t ? v4[1] : v4[0]; ia = t ? i4[1] : i4[0]; }
            { bool t = v4[3] > v4[2]; vb = t ? v4[3] : v4[2]; ib = t ? i4[3] : i4[2]; }
            bool tf = vb > va;
            float bv = tf ? vb : va;
            int   bi = tf ? ib : ia;

            unsigned bvb = __float_as_uint(bv);
            unsigned m = __reduce_max_sync(0xffffffffu, bvb);
            unsigned cand = (bvb == m) ? (unsigned)bi : 0x7FFFFFFFu;
            unsigned wmin = __reduce_min_sync(0xffffffffu, cand);

            int par = s & 1;
            if (lane == 0) { rv_[par][wid] = m; ri_[par][wid] = (int)wmin; }
            __syncthreads();
            unsigned v2 = (lane < 8) ? rv_[par][lane] : 0u;
            unsigned j2 = (lane < 8) ? (unsigned)ri_[par][lane] : 0x7FFFFFFFu;
            unsigned m2 = __reduce_max_sync(0xffffffffu, v2);
            unsigned c2 = (v2 == m2) ? j2 : 0x7FFFFFFFu;
            cur = (int)__reduce_min_sync(0xffffffffu, c2);
        }
        return;
    }

    // ================= select + mlp consumer =================
    int idx = bid - BZc;
    int s = idx >> 3, b = idx & 7;
    const float* pb = pos + (size_t)b * Nc * 3;

    // wait for fps to produce centroid s (thread 0 spins; others park at barrier)
    if (tid == 0) {
        int p;
        do {
            asm volatile("ld.acquire.gpu.u32 %0, [%1];" : "=r"(p) : "l"(g_prog + b) : "memory");
            if (p <= s) __nanosleep(128);
        } while (p <= s);
        s_ci = g_fps[b * NSc + s];
        s_cnt = 0;
    }
    __syncthreads();
    int ci = s_ci;
    if (tid < 3) scp[tid] = pb[3 * ci + tid];

    float sx = pb[3 * ci], sy = pb[3 * ci + 1], sz = pb[3 * ci + 2];
    float ss = __fadd_rn(__fadd_rn(__fmul_rn(sx, sx), __fmul_rn(sy, sy)), __fmul_rn(sz, sz));

    unsigned vr[16];
#pragma unroll
    for (int i = 0; i < 16; i++) {
        int j = tid + 256 * i;
        float xx = pb[3 * j], yy = pb[3 * j + 1], zz = pb[3 * j + 2];
        float pp = __fadd_rn(__fadd_rn(__fmul_rn(xx, xx), __fmul_rn(yy, yy)), __fmul_rn(zz, zz));
        float dot = __fadd_rn(__fadd_rn(__fmul_rn(sx, xx), __fmul_rn(sy, yy)), __fmul_rn(sz, zz));
        float d2 = __fadd_rn(__fadd_rn(ss, pp), __fmul_rn(-2.0f, dot));
        float dd = sqrtf(fmaxf(d2, 0.0f));
        vr[i] = __float_as_uint(dd);
    }

    // bisection on key space, one barrier per iter
    unsigned lo = 0u, hi = 0x40000000u;
    unsigned thr = hi;
    for (int it = 0; it < 32; it++) {
        unsigned m = (lo + hi) >> 1;
        int c = 0;
#pragma unroll
        for (int i = 0; i < 16; i++) c += (vr[i] < m) ? 1 : 0;
        c = (int)__reduce_add_sync(0xffffffffu, (unsigned)c);
        int par = it & 1;
        if (lane == 0) rv_[par][wid] = (unsigned)c;
        __syncthreads();
        int tot = (int)__reduce_add_sync(0xffffffffu, (lane < 8) ? rv_[par][lane] : 0u);
        if (tot >= Kc && tot <= 256) { thr = m; break; }
        if (tot < Kc) lo = m; else hi = m;
        if (hi - lo <= 1) { thr = hi; break; }
    }

#pragma unroll
    for (int i = 0; i < 16; i++) {
        if (vr[i] < thr) {
            int p = atomicAdd(&s_cnt, 1);
            if (p < CANDMAX) { u->sel.cand_v[p] = vr[i]; u->sel.cand_i[p] = tid + 256 * i; }
        }
    }
    __syncthreads();
    int c = s_cnt; if (c > CANDMAX) c = CANDMAX;

    // exact lexicographic (value,index) rank -> winners straight into smem
    for (int q0 = tid; q0 < c; q0 += 256) {
        unsigned vi = u->sel.cand_v[q0];
        int ji = u->sel.cand_i[q0];
        int r = 0;
        for (int q = 0; q < c; q++) {
            unsigned vq = u->sel.cand_v[q];
            int jq = u->sel.cand_i[q];
            r += (vq < vi || (vq == vi && jq < ji)) ? 1 : 0;
        }
        if (r < Kc) {
            nidx[r] = ji;
            smask[r] = (__uint_as_float(vi) <= Rc) ? 1 : 0;
        }
    }
    __syncthreads();

    // ---------------- MLP ----------------
    float* As = u->m.As;
    float* Bs = u->m.Bs;
    float* Mx = u->m.Mx;
    int w = wid;

    const float* xb = x + (size_t)b * Nc * CFc;
    for (int i = tid; i < 64 * 67; i += 256) {
        int k = i / 67, ch = i - k * 67;
        int id = nidx[k];
        float v = (ch < 3) ? (pb[3 * id + ch] - scp[ch]) : xb[(size_t)id * CFc + (ch - 3)];
        As[ch * 68 + k] = v;
    }
    __syncthreads();

    // ---- layer 1: 67 -> 64. warp slice: 16 o x 32 k; thread: 4k x 4o ----
    {
        int o0 = (w & 3) * 16 + (lane & 3) * 4;
        int k0 = (w >> 2) * 32 + (lane >> 2) * 4;
        float4 b4 = *(const float4*)(g_bb0 + o0);
        u64t aL[4], aH[4];
#pragma unroll
        for (int i = 0; i < 4; i++) { aL[i] = f2pk(b4.x, b4.y); aH[i] = f2pk(b4.z, b4.w); }
        for (int ch = 0; ch < 67; ch++) {
            float4 a = *(const float4*)(As + ch * 68 + k0);
            ulonglong2 wv = *(const ulonglong2*)(g_w0 + ch * 64 + o0);
            u64t d0 = f2dup(a.x); f2fma(aL[0], wv.x, d0); f2fma(aH[0], wv.y, d0);
            u64t d1 = f2dup(a.y); f2fma(aL[1], wv.x, d1); f2fma(aH[1], wv.y, d1);
            u64t d2 = f2dup(a.z); f2fma(aL[2], wv.x, d2); f2fma(aH[2], wv.y, d2);
            u64t d3 = f2dup(a.w); f2fma(aL[3], wv.x, d3); f2fma(aH[3], wv.y, d3);
        }
        float r[4][4];
#pragma unroll
        for (int i = 0; i < 4; i++) {
            f2unpk(aL[i], r[i][0], r[i][1]);
            f2unpk(aH[i], r[i][2], r[i][3]);
#pragma unroll
            for (int j = 0; j < 4; j++) r[i][j] = fmaxf(r[i][j], 0.f);
        }
#pragma unroll
        for (int j = 0; j < 4; j++)
            *(float4*)(Bs + (o0 + j) * 68 + k0) = make_float4(r[0][j], r[1][j], r[2][j], r[3][j]);
    }
    __syncthreads();

    // ---- layer 2: 64 -> 64, same tiling, Bs -> As ----
    {
        int o0 = (w & 3) * 16 + (lane & 3) * 4;
        int k0 = (w >> 2) * 32 + (lane >> 2) * 4;
        float4 b4 = *(const float4*)(g_bb1 + o0);
        u64t aL[4], aH[4];
#pragma unroll
        for (int i = 0; i < 4; i++) { aL[i] = f2pk(b4.x, b4.y); aH[i] = f2pk(b4.z, b4.w); }
        for (int ch = 0; ch < 64; ch++) {
            float4 a = *(const float4*)(Bs + ch * 68 + k0);
            ulonglong2 wv = *(const ulonglong2*)(g_w1 + ch * 64 + o0);
            u64t d0 = f2dup(a.x); f2fma(aL[0], wv.x, d0); f2fma(aH[0], wv.y, d0);
            u64t d1 = f2dup(a.y); f2fma(aL[1], wv.x, d1); f2fma(aH[1], wv.y, d1);
            u64t d2 = f2dup(a.z); f2fma(aL[2], wv.x, d2); f2fma(aH[2], wv.y, d2);
            u64t d3 = f2dup(a.w); f2fma(aL[3], wv.x, d3); f2fma(aH[3], wv.y, d3);
        }
        float r[4][4];
#pragma unroll
        for (int i = 0; i < 4; i++) {
            f2unpk(aL[i], r[i][0], r[i][1]);
            f2unpk(aH[i], r[i][2], r[i][3]);
#pragma unroll
            for (int j = 0; j < 4; j++) r[i][j] = fmaxf(r[i][j], 0.f);
        }
#pragma unroll
        for (int j = 0; j < 4; j++)
            *(float4*)(As + (o0 + j) * 68 + k0) = make_float4(r[0][j], r[1][j], r[2][j], r[3][j]);
    }
    __syncthreads();

    // ---- layer 3: 64 -> 128. warp slice: 32 o x 32 k; thread: 8k x 4o ----
    {
        int o0 = (w & 3) * 32 + (lane & 7) * 4;
        int k0 = (w >> 2) * 32 + (lane >> 3) * 8;
        float4 b4 = *(const float4*)(g_bb2 + o0);
        u64t aL[8], aH[8];
#pragma unroll
        for (int i = 0; i < 8; i++) { aL[i] = f2pk(b4.x, b4.y); aH[i] = f2pk(b4.z, b4.w); }
        for (int ch = 0; ch < 64; ch++) {
            float4 a0 = *(const float4*)(As + ch * 68 + k0);
            float4 a1 = *(const float4*)(As + ch * 68 + k0 + 4);
            ulonglong2 wv = *(const ulonglong2*)(g_w2 + ch * 128 + o0);
            u64t d;
            d = f2dup(a0.x); f2fma(aL[0], wv.x, d); f2fma(aH[0], wv.y, d);
            d = f2dup(a0.y); f2fma(aL[1], wv.x, d); f2fma(aH[1], wv.y, d);
            d = f2dup(a0.z); f2fma(aL[2], wv.x, d); f2fma(aH[2], wv.y, d);
            d = f2dup(a0.w); f2fma(aL[3], wv.x, d); f2fma(aH[3], wv.y, d);
            d = f2dup(a1.x); f2fma(aL[4], wv.x, d); f2fma(aH[4], wv.y, d);
            d = f2dup(a1.y); f2fma(aL[5], wv.x, d); f2fma(aH[5], wv.y, d);
            d = f2dup(a1.z); f2fma(aL[6], wv.x, d); f2fma(aH[6], wv.y, d);
            d = f2dup(a1.w); f2fma(aL[7], wv.x, d); f2fma(aH[7], wv.y, d);
        }
        float4 mx = make_float4(NEGc, NEGc, NEGc, NEGc);
#pragma unroll
        for (int i = 0; i < 8; i++) {
            if (smask[k0 + i]) {
                float r0, r1, r2, r3;
                f2unpk(aL[i], r0, r1);
                f2unpk(aH[i], r2, r3);
                mx.x = fmaxf(mx.x, fmaxf(r0, 0.f));
                mx.y = fmaxf(mx.y, fmaxf(r1, 0.f));
                mx.z = fmaxf(mx.z, fmaxf(r2, 0.f));
                mx.w = fmaxf(mx.w, fmaxf(r3, 0.f));
            }
        }
        int row = (w >> 2) * 4 + (lane >> 3);
        *(float4*)(Mx + row * 128 + o0) = mx;
    }
    __syncthreads();

    if (tid < 128) {
        float v = NEGc;
#pragma unroll
        for (int q = 0; q < 8; q++) v = fmaxf(v, Mx[q * 128 + tid]);
        out[(size_t)(b * NSc + s) * 128 + tid] = v;
    }
}

// ---------------- launch ----------------
extern "C" void kernel_launch(void* const* d_in, const int* in_sizes, int n_in,
                              void* d_out, int out_size)
{
    const float* x   = (const float*)d_in[0];
    const float* pos = (const float*)d_in[1];
    const float* W0 = (const float*)d_in[2];
    const float* b0 = (const float*)d_in[3];
    const float* g0 = (const float*)d_in[4];
    const float* be0 = (const float*)d_in[5];
    const float* rm0 = (const float*)d_in[6];
    const float* rv0 = (const float*)d_in[7];
    const float* W1 = (const float*)d_in[8];
    const float* b1 = (const float*)d_in[9];
    const float* g1 = (const float*)d_in[10];
    const float* be1 = (const float*)d_in[11];
    const float* rm1 = (const float*)d_in[12];
    const float* rv1 = (const float*)d_in[13];
    const float* W2 = (const float*)d_in[14];
    const float* b2 = (const float*)d_in[15];
    const float* g2 = (const float*)d_in[16];
    const float* be2 = (const float*)d_in[17];
    const float* rm2 = (const float*)d_in[18];
    const float* rv2 = (const float*)d_in[19];

    float* out = (float*)d_out;
    float* out_sp = out + (size_t)BZc * NSc * 128;  // tuple output 2: sampled_pos

    const int MEGA_SMEM = (int)sizeof(SU);  // 48 KB union

    cudaFuncSetAttribute(mega_kernel, cudaFuncAttributeMaxDynamicSharedMemorySize, MEGA_SMEM);

    fold_kernel<<<40, 256>>>(W0, b0, g0, be0, rm0, rv0,
                             W1, b1, g1, be1, rm1, rv1,
                             W2, b2, g2, be2, rm2, rv2);
    mega_kernel<<<BZc + BZc * NSc, 256, MEGA_SMEM>>>(x, pos, out, out_sp);
}

// round 12
// speedup vs baseline: 1.1641x; 1.1175x over previous
#include <cuda_runtime.h>
#include <cuda_bf16.h>

#define BZc 8
#define Nc 4096
#define CFc 64
#define NSc 1024
#define Kc 64
#define EPSc 1e-5f
#define NEGc -1e8f
#define Rc 0.2f
#define CANDMAX 1280
#define FPS_SMEM_PAD 200704   // 196 KB: monopolize the SM (consumer smem ~39KB can't fit)

typedef unsigned long long u64t;

// ---------------- f32x2 packed helpers (sm_100+) ----------------
__device__ __forceinline__ u64t f2pk(float lo, float hi) {
    u64t r; asm("mov.b64 %0,{%1,%2};" : "=l"(r) : "f"(lo), "f"(hi)); return r;
}
__device__ __forceinline__ u64t f2dup(float a) {
    u64t r; asm("mov.b64 %0,{%1,%1};" : "=l"(r) : "f"(a)); return r;
}
__device__ __forceinline__ void f2unpk(u64t v, float& lo, float& hi) {
    asm("mov.b64 {%0,%1},%2;" : "=f"(lo), "=f"(hi) : "l"(v));
}
__device__ __forceinline__ u64t f2add(u64t a, u64t b) {
    u64t r; asm("add.rn.f32x2 %0,%1,%2;" : "=l"(r) : "l"(a), "l"(b)); return r;
}
__device__ __forceinline__ u64t f2mul(u64t a, u64t b) {
    u64t r; asm("mul.rn.f32x2 %0,%1,%2;" : "=l"(r) : "l"(a), "l"(b)); return r;
}
__device__ __forceinline__ void f2fma(u64t& acc, u64t w, u64t a) {
    asm("fma.rn.f32x2 %0,%1,%2,%0;" : "+l"(acc) : "l"(w), "l"(a));
}

// ---------------- scratch (no allocs allowed) ----------------
__device__ int g_fps[BZc * NSc];
__device__ int g_prog[BZc];
__device__ __align__(16) float g_w0[67 * 64];
__device__ __align__(16) float g_bb0[64];
__device__ __align__(16) float g_w1[64 * 64];
__device__ __align__(16) float g_bb1[64];
__device__ __align__(16) float g_w2[64 * 128];
__device__ __align__(16) float g_bb2[128];

// ---------------- fold BN (eval) into weights; reset fps progress ----------------
__global__ void fold_kernel(
    const float* __restrict__ W0, const float* __restrict__ b0, const float* __restrict__ g0,
    const float* __restrict__ be0, const float* __restrict__ rm0, const float* __restrict__ rv0,
    const float* __restrict__ W1, const float* __restrict__ b1, const float* __restrict__ g1,
    const float* __restrict__ be1, const float* __restrict__ rm1, const float* __restrict__ rv1,
    const float* __restrict__ W2, const float* __restrict__ b2, const float* __restrict__ g2,
    const float* __restrict__ be2, const float* __restrict__ rm2, const float* __restrict__ rv2)
{
    int t = blockIdx.x * blockDim.x + threadIdx.x;
    int stride = gridDim.x * blockDim.x;
    if (t < BZc) g_prog[t] = 0;
    for (int i = t; i < 67 * 64; i += stride) {
        int o = i & 63;
        g_w0[i] = W0[i] * (g0[o] * rsqrtf(rv0[o] + EPSc));
    }
    for (int i = t; i < 64; i += stride) {
        float sc = g0[i] * rsqrtf(rv0[i] + EPSc);
        g_bb0[i] = (b0[i] - rm0[i]) * sc + be0[i];
    }
    for (int i = t; i < 64 * 64; i += stride) {
        int o = i & 63;
        g_w1[i] = W1[i] * (g1[o] * rsqrtf(rv1[o] + EPSc));
    }
    for (int i = t; i < 64; i += stride) {
        float sc = g1[i] * rsqrtf(rv1[i] + EPSc);
        g_bb1[i] = (b1[i] - rm1[i]) * sc + be1[i];
    }
    for (int i = t; i < 64 * 128; i += stride) {
        int o = i & 127;
        g_w2[i] = W2[i] * (g2[o] * rsqrtf(rv2[o] + EPSc));
    }
    for (int i = t; i < 128; i += stride) {
        float sc = g2[i] * rsqrtf(rv2[i] + EPSc);
        g_bb2[i] = (b2[i] - rm2[i]) * sc + be2[i];
    }
}

// ---------------- farthest point sampling (producer, dedicated SMs) ----------------
__global__ void __launch_bounds__(256) fps_kernel(const float* __restrict__ pos,
                                                  float* __restrict__ out_sp)
{
    extern __shared__ float sm[];
    float* px = sm;
    float* py = sm + Nc;
    float* pz = sm + 2 * Nc;
    __shared__ unsigned rv_[2][8];
    __shared__ int      ri_[2][8];

    int b = blockIdx.x;
    int tid = threadIdx.x;
    int lane = tid & 31, wid = tid >> 5;
    const float* pb = pos + (size_t)b * Nc * 3;

    u64t xp[8], yp[8], zp[8];
    float ld[16];
#pragma unroll
    for (int p = 0; p < 8; p++) {
        int j0 = tid + 256 * (2 * p);
        int j1 = tid + 256 * (2 * p + 1);
        float x0 = pb[3 * j0], y0 = pb[3 * j0 + 1], z0 = pb[3 * j0 + 2];
        float x1 = pb[3 * j1], y1 = pb[3 * j1 + 1], z1 = pb[3 * j1 + 2];
        px[j0] = x0; py[j0] = y0; pz[j0] = z0;
        px[j1] = x1; py[j1] = y1; pz[j1] = z1;
        xp[p] = f2pk(x0, x1); yp[p] = f2pk(y0, y1); zp[p] = f2pk(z0, z1);
        ld[2 * p] = 1e10f; ld[2 * p + 1] = 1e10f;
    }
    __syncthreads();

    // allow the consumer kernel to launch now (PDL)
    cudaTriggerProgrammaticLaunchCompletion();

    int cur = 0;
    for (int s = 0; s < NSc; s++) {
        float cx = px[cur], cy = py[cur], cz = pz[cur];
        if (tid == 0) {
            g_fps[b * NSc + s] = cur;
            out_sp[(b * NSc + s) * 3 + 0] = cx;
            out_sp[(b * NSc + s) * 3 + 1] = cy;
            out_sp[(b * NSc + s) * 3 + 2] = cz;
            int np = s + 1;
            asm volatile("st.release.gpu.u32 [%0], %1;" :: "l"(g_prog + b), "r"(np) : "memory");
        }
        u64t ncx = f2dup(-cx), ncy = f2dup(-cy), ncz = f2dup(-cz);
#pragma unroll
        for (int p = 0; p < 8; p++) {
            u64t dx = f2add(xp[p], ncx);
            u64t dy = f2add(yp[p], ncy);
            u64t dz = f2add(zp[p], ncz);
            u64t d2 = f2add(f2add(f2mul(dx, dx), f2mul(dy, dy)), f2mul(dz, dz));
            float s0, s1;
            f2unpk(d2, s0, s1);
            ld[2 * p] = fminf(ld[2 * p], s0);
            ld[2 * p + 1] = fminf(ld[2 * p + 1], s1);
        }
        // tournament-tree argmax over 16 values, lowest index wins ties
        float v8[8]; int i8[8];
#pragma unroll
        for (int i = 0; i < 8; i++) {
            float a = ld[2 * i], bb2_ = ld[2 * i + 1];
            bool t = bb2_ > a;
            v8[i] = t ? bb2_ : a;
            i8[i] = tid + 256 * (2 * i + (t ? 1 : 0));
        }
        float v4[4]; int i4[4];
#pragma unroll
        for (int i = 0; i < 4; i++) {
            bool t = v8[2 * i + 1] > v8[2 * i];
            v4[i] = t ? v8[2 * i + 1] : v8[2 * i];
            i4[i] = t ? i8[2 * i + 1] : i8[2 * i];
        }
        float va, vb; int ia, ib;
        { bool t = v4[1] > v4[0]; va = t ? v4[1] : v4[0]; ia = t ? i4[1] : i4[0]; }
        { bool t = v4[3] > v4[2]; vb = t ? v4[3] : v4[2]; ib = t ? i4[3] : i4[2]; }
        bool tf = vb > va;
        float bv = tf ? vb : va;
        int   bi = tf ? ib : ia;

        unsigned bvb = __float_as_uint(bv);
        unsigned m = __reduce_max_sync(0xffffffffu, bvb);
        unsigned cand = (bvb == m) ? (unsigned)bi : 0x7FFFFFFFu;
        unsigned wmin = __reduce_min_sync(0xffffffffu, cand);

        int par = s & 1;
        if (lane == 0) { rv_[par][wid] = m; ri_[par][wid] = (int)wmin; }
        __syncthreads();
        unsigned v2 = (lane < 8) ? rv_[par][lane] : 0u;
        unsigned j2 = (lane < 8) ? (unsigned)ri_[par][lane] : 0x7FFFFFFFu;
        unsigned m2 = __reduce_max_sync(0xffffffffu, v2);
        unsigned c2 = (v2 == m2) ? j2 : 0x7FFFFFFFu;
        cur = (int)__reduce_min_sync(0xffffffffu, c2);
    }
}

// ---------------- consumer: select + mlp, spin on fps progress ----------------
struct SSel { unsigned cand_v[CANDMAX]; int cand_i[CANDMAX]; };
struct SMlp { float As[67 * 68]; float Bs[64 * 68]; float Mx[8 * 128]; };
union SUc { SSel sel; SMlp m; };

__global__ void __launch_bounds__(256, 3) smlp_kernel(const float* __restrict__ x,
                                                      const float* __restrict__ pos,
                                                      float* __restrict__ out)
{
    __shared__ SUc u;
    __shared__ unsigned rv_[2][8];
    __shared__ int s_cnt, s_ci;
    __shared__ int nidx[64];
    __shared__ unsigned char smask[64];
    __shared__ float scp[3];

    int b = blockIdx.x, s = blockIdx.y, tid = threadIdx.x;
    int lane = tid & 31, wid = tid >> 5;
    const float* pb = pos + (size_t)b * Nc * 3;

    // wait for fps to produce centroid s (thread 0 spins; others park at barrier)
    if (tid == 0) {
        int p;
        do {
            asm volatile("ld.acquire.gpu.u32 %0, [%1];" : "=r"(p) : "l"(g_prog + b) : "memory");
            if (p <= s) __nanosleep(256);
        } while (p <= s);
        s_ci = g_fps[b * NSc + s];
        s_cnt = 0;
    }
    __syncthreads();
    int ci = s_ci;
    if (tid < 3) scp[tid] = pb[3 * ci + tid];

    float sx = pb[3 * ci], sy = pb[3 * ci + 1], sz = pb[3 * ci + 2];
    float ss = __fadd_rn(__fadd_rn(__fmul_rn(sx, sx), __fmul_rn(sy, sy)), __fmul_rn(sz, sz));

    unsigned vr[16];
#pragma unroll
    for (int i = 0; i < 16; i++) {
        int j = tid + 256 * i;
        float xx = pb[3 * j], yy = pb[3 * j + 1], zz = pb[3 * j + 2];
        float pp = __fadd_rn(__fadd_rn(__fmul_rn(xx, xx), __fmul_rn(yy, yy)), __fmul_rn(zz, zz));
        float dot = __fadd_rn(__fadd_rn(__fmul_rn(sx, xx), __fmul_rn(sy, yy)), __fmul_rn(sz, zz));
        float d2 = __fadd_rn(__fadd_rn(ss, pp), __fmul_rn(-2.0f, dot));
        float dd = sqrtf(fmaxf(d2, 0.0f));
        vr[i] = __float_as_uint(dd);
    }

    // bisection on key space, one barrier per iter
    unsigned lo = 0u, hi = 0x40000000u;
    unsigned thr = hi;
    for (int it = 0; it < 32; it++) {
        unsigned m = (lo + hi) >> 1;
        int c = 0;
#pragma unroll
        for (int i = 0; i < 16; i++) c += (vr[i] < m) ? 1 : 0;
        c = (int)__reduce_add_sync(0xffffffffu, (unsigned)c);
        int par = it & 1;
        if (lane == 0) rv_[par][wid] = (unsigned)c;
        __syncthreads();
        int tot = (int)__reduce_add_sync(0xffffffffu, (lane < 8) ? rv_[par][lane] : 0u);
        if (tot >= Kc && tot <= 256) { thr = m; break; }
        if (tot < Kc) lo = m; else hi = m;
        if (hi - lo <= 1) { thr = hi; break; }
    }

#pragma unroll
    for (int i = 0; i < 16; i++) {
        if (vr[i] < thr) {
            int p = atomicAdd(&s_cnt, 1);
            if (p < CANDMAX) { u.sel.cand_v[p] = vr[i]; u.sel.cand_i[p] = tid + 256 * i; }
        }
    }
    __syncthreads();
    int c = s_cnt; if (c > CANDMAX) c = CANDMAX;

    // exact lexicographic (value,index) rank -> winners straight into smem
    for (int q0 = tid; q0 < c; q0 += 256) {
        unsigned vi = u.sel.cand_v[q0];
        int ji = u.sel.cand_i[q0];
        int r = 0;
        for (int q = 0; q < c; q++) {
            unsigned vq = u.sel.cand_v[q];
            int jq = u.sel.cand_i[q];
            r += (vq < vi || (vq == vi && jq < ji)) ? 1 : 0;
        }
        if (r < Kc) {
            nidx[r] = ji;
            smask[r] = (__uint_as_float(vi) <= Rc) ? 1 : 0;
        }
    }
    __syncthreads();

    // ---------------- MLP ----------------
    float* As = u.m.As;
    float* Bs = u.m.Bs;
    float* Mx = u.m.Mx;
    int w = wid;

    const float* xb = x + (size_t)b * Nc * CFc;
    for (int i = tid; i < 64 * 67; i += 256) {
        int k = i / 67, ch = i - k * 67;
        int id = nidx[k];
        float v = (ch < 3) ? (pb[3 * id + ch] - scp[ch]) : xb[(size_t)id * CFc + (ch - 3)];
        As[ch * 68 + k] = v;
    }
    __syncthreads();

    // ---- layer 1: 67 -> 64. warp slice: 16 o x 32 k; thread: 4k x 4o ----
    {
        int o0 = (w & 3) * 16 + (lane & 3) * 4;
        int k0 = (w >> 2) * 32 + (lane >> 2) * 4;
        float4 b4 = *(const float4*)(g_bb0 + o0);
        u64t aL[4], aH[4];
#pragma unroll
        for (int i = 0; i < 4; i++) { aL[i] = f2pk(b4.x, b4.y); aH[i] = f2pk(b4.z, b4.w); }
        for (int ch = 0; ch < 67; ch++) {
            float4 a = *(const float4*)(As + ch * 68 + k0);
            ulonglong2 wv = *(const ulonglong2*)(g_w0 + ch * 64 + o0);
            u64t d0 = f2dup(a.x); f2fma(aL[0], wv.x, d0); f2fma(aH[0], wv.y, d0);
            u64t d1 = f2dup(a.y); f2fma(aL[1], wv.x, d1); f2fma(aH[1], wv.y, d1);
            u64t d2 = f2dup(a.z); f2fma(aL[2], wv.x, d2); f2fma(aH[2], wv.y, d2);
            u64t d3 = f2dup(a.w); f2fma(aL[3], wv.x, d3); f2fma(aH[3], wv.y, d3);
        }
        float r[4][4];
#pragma unroll
        for (int i = 0; i < 4; i++) {
            f2unpk(aL[i], r[i][0], r[i][1]);
            f2unpk(aH[i], r[i][2], r[i][3]);
#pragma unroll
            for (int j = 0; j < 4; j++) r[i][j] = fmaxf(r[i][j], 0.f);
        }
#pragma unroll
        for (int j = 0; j < 4; j++)
            *(float4*)(Bs + (o0 + j) * 68 + k0) = make_float4(r[0][j], r[1][j], r[2][j], r[3][j]);
    }
    __syncthreads();

    // ---- layer 2: 64 -> 64, same tiling, Bs -> As ----
    {
        int o0 = (w & 3) * 16 + (lane & 3) * 4;
        int k0 = (w >> 2) * 32 + (lane >> 2) * 4;
        float4 b4 = *(const float4*)(g_bb1 + o0);
        u64t aL[4], aH[4];
#pragma unroll
        for (int i = 0; i < 4; i++) { aL[i] = f2pk(b4.x, b4.y); aH[i] = f2pk(b4.z, b4.w); }
        for (int ch = 0; ch < 64; ch++) {
            float4 a = *(const float4*)(Bs + ch * 68 + k0);
            ulonglong2 wv = *(const ulonglong2*)(g_w1 + ch * 64 + o0);
            u64t d0 = f2dup(a.x); f2fma(aL[0], wv.x, d0); f2fma(aH[0], wv.y, d0);
            u64t d1 = f2dup(a.y); f2fma(aL[1], wv.x, d1); f2fma(aH[1], wv.y, d1);
            u64t d2 = f2dup(a.z); f2fma(aL[2], wv.x, d2); f2fma(aH[2], wv.y, d2);
            u64t d3 = f2dup(a.w); f2fma(aL[3], wv.x, d3); f2fma(aH[3], wv.y, d3);
        }
        float r[4][4];
#pragma unroll
        for (int i = 0; i < 4; i++) {
            f2unpk(aL[i], r[i][0], r[i][1]);
            f2unpk(aH[i], r[i][2], r[i][3]);
#pragma unroll
            for (int j = 0; j < 4; j++) r[i][j] = fmaxf(r[i][j], 0.f);
        }
#pragma unroll
        for (int j = 0; j < 4; j++)
            *(float4*)(As + (o0 + j) * 68 + k0) = make_float4(r[0][j], r[1][j], r[2][j], r[3][j]);
    }
    __syncthreads();

    // ---- layer 3: 64 -> 128. warp slice: 32 o x 32 k; thread: 8k x 4o ----
    {
        int o0 = (w & 3) * 32 + (lane & 7) * 4;
        int k0 = (w >> 2) * 32 + (lane >> 3) * 8;
        float4 b4 = *(const float4*)(g_bb2 + o0);
        u64t aL[8], aH[8];
#pragma unroll
        for (int i = 0; i < 8; i++) { aL[i] = f2pk(b4.x, b4.y); aH[i] = f2pk(b4.z, b4.w); }
        for (int ch = 0; ch < 64; ch++) {
            float4 a0 = *(const float4*)(As + ch * 68 + k0);
            float4 a1 = *(const float4*)(As + ch * 68 + k0 + 4);
            ulonglong2 wv = *(const ulonglong2*)(g_w2 + ch * 128 + o0);
            u64t d;
            d = f2dup(a0.x); f2fma(aL[0], wv.x, d); f2fma(aH[0], wv.y, d);
            d = f2dup(a0.y); f2fma(aL[1], wv.x, d); f2fma(aH[1], wv.y, d);
            d = f2dup(a0.z); f2fma(aL[2], wv.x, d); f2fma(aH[2], wv.y, d);
            d = f2dup(a0.w); f2fma(aL[3], wv.x, d); f2fma(aH[3], wv.y, d);
            d = f2dup(a1.x); f2fma(aL[4], wv.x, d); f2fma(aH[4], wv.y, d);
            d = f2dup(a1.y); f2fma(aL[5], wv.x, d); f2fma(aH[5], wv.y, d);
            d = f2dup(a1.z); f2fma(aL[6], wv.x, d); f2fma(aH[6], wv.y, d);
            d = f2dup(a1.w); f2fma(aL[7], wv.x, d); f2fma(aH[7], wv.y, d);
        }
        float4 mx = make_float4(NEGc, NEGc, NEGc, NEGc);
#pragma unroll
        for (int i = 0; i < 8; i++) {
            if (smask[k0 + i]) {
                float r0, r1, r2, r3;
                f2unpk(aL[i], r0, r1);
                f2unpk(aH[i], r2, r3);
                mx.x = fmaxf(mx.x, fmaxf(r0, 0.f));
                mx.y = fmaxf(mx.y, fmaxf(r1, 0.f));
                mx.z = fmaxf(mx.z, fmaxf(r2, 0.f));
                mx.w = fmaxf(mx.w, fmaxf(r3, 0.f));
            }
        }
        int row = (w >> 2) * 4 + (lane >> 3);
        *(float4*)(Mx + row * 128 + o0) = mx;
    }
    __syncthreads();

    if (tid < 128) {
        float v = NEGc;
#pragma unroll
        for (int q = 0; q < 8; q++) v = fmaxf(v, Mx[q * 128 + tid]);
        out[(size_t)(b * NSc + s) * 128 + tid] = v;
    }
}

// ---------------- launch ----------------
extern "C" void kernel_launch(void* const* d_in, const int* in_sizes, int n_in,
                              void* d_out, int out_size)
{
    const float* x   = (const float*)d_in[0];
    const float* pos = (const float*)d_in[1];
    const float* W0 = (const float*)d_in[2];
    const float* b0 = (const float*)d_in[3];
    const float* g0 = (const float*)d_in[4];
    const float* be0 = (const float*)d_in[5];
    const float* rm0 = (const float*)d_in[6];
    const float* rv0 = (const float*)d_in[7];
    const float* W1 = (const float*)d_in[8];
    const float* b1 = (const float*)d_in[9];
    const float* g1 = (const float*)d_in[10];
    const float* be1 = (const float*)d_in[11];
    const float* rm1 = (const float*)d_in[12];
    const float* rv1 = (const float*)d_in[13];
    const float* W2 = (const float*)d_in[14];
    const float* b2 = (const float*)d_in[15];
    const float* g2 = (const float*)d_in[16];
    const float* be2 = (const float*)d_in[17];
    const float* rm2 = (const float*)d_in[18];
    const float* rv2 = (const float*)d_in[19];

    float* out = (float*)d_out;
    float* out_sp = out + (size_t)BZc * NSc * 128;  // tuple output 2: sampled_pos

    cudaFuncSetAttribute(fps_kernel, cudaFuncAttributeMaxDynamicSharedMemorySize, FPS_SMEM_PAD);

    fold_kernel<<<40, 256>>>(W0, b0, g0, be0, rm0, rv0,
                             W1, b1, g1, be1, rm1, rv1,
                             W2, b2, g2, be2, rm2, rv2);

    // producer: 8 CTAs, each hogging ~196KB smem -> dedicated SMs
    fps_kernel<<<BZc, 256, FPS_SMEM_PAD>>>(pos, out_sp);

    // consumer: PDL so it launches while fps is still running
    cudaLaunchConfig_t cfg = {};
    cfg.gridDim = dim3(BZc, NSc, 1);
    cfg.blockDim = dim3(256, 1, 1);
    cfg.dynamicSmemBytes = 0;
    cfg.stream = 0;
    cudaLaunchAttribute at[1];
    at[0].id = cudaLaunchAttributeProgrammaticStreamSerialization;
    at[0].val.programmaticStreamSerializationAllowed = 1;
    cfg.attrs = at;
    cfg.numAttrs = 1;
    cudaLaunchKernelEx(&cfg, smlp_kernel, x, pos, out);
}